// round 8
// baseline (speedup 1.0000x reference)
#include <cuda_runtime.h>

#define NMAX 50000
#define C 96

__device__ float g_v[NMAX * C];
__device__ float g_Q1[NMAX * 8];
__device__ float g_K1[NMAX * 8];
__device__ float4 g_c4[NMAX];

// ---- f32x2 packed-math helpers (sm_103a) ----
typedef unsigned long long ull;
#define FFMA2(d, a, b, c) \
    asm("fma.rn.f32x2 %0, %1, %2, %3;" : "=l"(d) : "l"(a), "l"(b), "l"(c))
#define LDS2X64(a, b, addr) \
    asm volatile("ld.shared.v2.u64 {%0, %1}, [%2];" : "=l"(a), "=l"(b) : "r"(addr))
#define DUP2(d, f) \
    asm("mov.b64 %0, {%1, %1};" : "=l"(d) : "r"(__float_as_uint(f)))
#define UNPK(lo, hi, p) do { unsigned _ul, _uh; \
    asm("mov.b64 {%0, %1}, %2;" : "=r"(_ul), "=r"(_uh) : "l"(p)); \
    lo = __uint_as_float(_ul); hi = __uint_as_float(_uh); } while (0)

__device__ __forceinline__ unsigned smaddr(const void* p) {
    unsigned r;
    asm("{.reg .u64 t; cvta.to.shared.u64 t, %1; cvt.u32.u64 %0, t;}"
        : "=r"(r) : "l"(p));
    return r;
}

// ---------------------------------------------------------------------------
// Kernel A: v = feat@Wv+bv, Q1 = relu(bn(feat@Wq+bq))@Ww1f, K1 likewise.
// 64 rows/block, 192 threads, 8x4 register tile, f32x2.
// Warp map tx=tid/8, ty=tid%8 -> feat loads 8-distinct (1 wf), Ws 4-distinct.
// Also packs coord into g_c4.
// ---------------------------------------------------------------------------
#define A_FEATT 0            // 96*68
#define A_WS    6528         // 96*96
#define A_W1T   15744        // Ww1fT[6][100] = 600
#define A_ROWS  16344        // 64*100
#define A_FLOATS 22744

__global__ __launch_bounds__(192) void qkv_kernel(
    const float* __restrict__ feat, const float* __restrict__ coord,
    const float* __restrict__ Wq, const float* __restrict__ bq,
    const float* __restrict__ gq, const float* __restrict__ betaq,
    const float* __restrict__ Wk, const float* __restrict__ bk,
    const float* __restrict__ gk, const float* __restrict__ betak,
    const float* __restrict__ Wv, const float* __restrict__ bv,
    const float* __restrict__ Ww1, const float* __restrict__ gw,
    int n)
{
    extern __shared__ float sm[];
    float* featT = sm + A_FEATT;
    float* Ws    = sm + A_WS;
    float* Ww1fT = sm + A_W1T;   // [6][100] row-major by g
    float* rows  = sm + A_ROWS;  // [64][100]
    const int tid = threadIdx.x;
    const int tx = tid >> 3, ty = tid & 7;   // 24 col-groups x 8 row-groups
    const int base = blockIdx.x * 64;

    // pack coord4 for this block's rows
    if (tid < 64) {
        int row = base + tid;
        if (row < n) {
            float4 c;
            c.x = coord[row * 3 + 0];
            c.y = coord[row * 3 + 1];
            c.z = coord[row * 3 + 2];
            c.w = 0.f;
            g_c4[row] = c;
        }
    }

    for (int i = tid; i < 64 * 96; i += 192) {
        int r = i / 96, j = i % 96;
        featT[j * 68 + r] = (base + r < n) ? feat[(base + r) * 96 + j] : 0.f;
    }
    for (int i = tid; i < 600; i += 192) {
        int g = i / 100, c = i % 100;
        Ww1fT[i] = (c < 96) ? Ww1[c * 6 + g] * (gw[g] * rsqrtf(1.00001f)) : 0.f;
    }

    const unsigned fbase  = smaddr(featT) + 8 * ty * 4;
    const unsigned rows_b = smaddr(rows);
    const unsigned w1t_b  = smaddr(Ww1fT);

    for (int m = 0; m < 3; m++) {
        const float* W = (m == 0) ? Wq : ((m == 1) ? Wk : Wv);
        __syncthreads();
        for (int i = tid; i < 96 * 96; i += 192) Ws[i] = W[i];
        __syncthreads();

        ull acc2[4][4];
        #pragma unroll
        for (int p = 0; p < 4; p++)
            #pragma unroll
            for (int b = 0; b < 4; b++) acc2[p][b] = 0ULL;

        unsigned fa = fbase;
        #pragma unroll 4
        for (int j = 0; j < 96; j++) {
            ull f01, f23, f45, f67;
            LDS2X64(f01, f23, fa);
            LDS2X64(f45, f67, fa + 16);
            fa += 272;
            float4 w4 = *(const float4*)&Ws[j * 96 + 4 * tx];
            ull wd0, wd1, wd2, wd3;
            DUP2(wd0, w4.x); DUP2(wd1, w4.y); DUP2(wd2, w4.z); DUP2(wd3, w4.w);
            FFMA2(acc2[0][0], f01, wd0, acc2[0][0]);
            FFMA2(acc2[0][1], f01, wd1, acc2[0][1]);
            FFMA2(acc2[0][2], f01, wd2, acc2[0][2]);
            FFMA2(acc2[0][3], f01, wd3, acc2[0][3]);
            FFMA2(acc2[1][0], f23, wd0, acc2[1][0]);
            FFMA2(acc2[1][1], f23, wd1, acc2[1][1]);
            FFMA2(acc2[1][2], f23, wd2, acc2[1][2]);
            FFMA2(acc2[1][3], f23, wd3, acc2[1][3]);
            FFMA2(acc2[2][0], f45, wd0, acc2[2][0]);
            FFMA2(acc2[2][1], f45, wd1, acc2[2][1]);
            FFMA2(acc2[2][2], f45, wd2, acc2[2][2]);
            FFMA2(acc2[2][3], f45, wd3, acc2[2][3]);
            FFMA2(acc2[3][0], f67, wd0, acc2[3][0]);
            FFMA2(acc2[3][1], f67, wd1, acc2[3][1]);
            FFMA2(acc2[3][2], f67, wd2, acc2[3][2]);
            FFMA2(acc2[3][3], f67, wd3, acc2[3][3]);
        }

        float acc[8][4];
        #pragma unroll
        for (int p = 0; p < 4; p++)
            #pragma unroll
            for (int b = 0; b < 4; b++)
                UNPK(acc[2 * p][b], acc[2 * p + 1][b], acc2[p][b]);

        if (m == 2) {
            int c = 4 * tx;
            float4 bb = *(const float4*)&bv[c];
            #pragma unroll
            for (int a = 0; a < 8; a++) {
                int row = base + 8 * ty + a;
                if (row < n) {
                    float4 o = {acc[a][0] + bb.x, acc[a][1] + bb.y,
                                acc[a][2] + bb.z, acc[a][3] + bb.w};
                    *(float4*)&g_v[row * 96 + c] = o;
                }
            }
        } else {
            int c = 4 * tx;
            const float* bsrc = (m == 0) ? bq : bk;
            const float* gsrc = (m == 0) ? gq : gk;
            const float* besrc = (m == 0) ? betaq : betak;
            float4 bb = *(const float4*)&bsrc[c];
            float4 gg = *(const float4*)&gsrc[c];
            float4 be = *(const float4*)&besrc[c];
            float rs = rsqrtf(1.00001f);
            float aa[4] = {gg.x * rs, gg.y * rs, gg.z * rs, gg.w * rs};
            float bba[4] = {bb.x, bb.y, bb.z, bb.w};
            float bea[4] = {be.x, be.y, be.z, be.w};
            #pragma unroll
            for (int a = 0; a < 8; a++) {
                float4 o;
                o.x = fmaxf((acc[a][0] + bba[0]) * aa[0] + bea[0], 0.f);
                o.y = fmaxf((acc[a][1] + bba[1]) * aa[1] + bea[1], 0.f);
                o.z = fmaxf((acc[a][2] + bba[2]) * aa[2] + bea[2], 0.f);
                o.w = fmaxf((acc[a][3] + bba[3]) * aa[3] + bea[3], 0.f);
                *(float4*)&rows[(8 * ty + a) * 100 + c] = o;
            }
            __syncthreads();
            float* dst = (m == 0) ? g_Q1 : g_K1;
            #pragma unroll
            for (int rr = 0; rr < 2; rr++) {
                int i = rr * 192 + tid;
                int r = i / 6, g = i % 6;
                ull a01 = 0ULL, a23 = 0ULL;
                unsigned rb = rows_b + r * 400;
                unsigned wb = w1t_b + g * 400;
                #pragma unroll
                for (int t = 0; t < 24; t++) {
                    ull r01, r23, w01, w23;
                    LDS2X64(r01, r23, rb); rb += 16;
                    LDS2X64(w01, w23, wb); wb += 16;
                    FFMA2(a01, r01, w01, a01);
                    FFMA2(a23, r23, w23, a23);
                }
                float l0, l1v, l2v, l3;
                UNPK(l0, l1v, a01); UNPK(l2v, l3, a23);
                if (base + r < n)
                    dst[(base + r) * 8 + g] = (l0 + l2v) + (l1v + l3);
            }
        }
    }
}

// ---------------------------------------------------------------------------
// Kernel B: fused attention. 384 threads = 4 point-lanes x 96. (R7 + coord4)
// ---------------------------------------------------------------------------
#define SH_WP2T 0        // [96][100]
#define SH_FT   9600     // [6][100]
#define SH_WP1F 10200    // [96][4]
#define SH_BP2  10584    // 96
#define SH_WW2  10680    // 40
#define SH_BW2  10720    // 8
#define SH_CB   10728    // 8
#define SH_W1F  10736    // 576
#define SH_PART 11312    // [16][96]
#define SH_LANE 12848
// per-lane (floats)
#define L_HT   0         // hT[16][100]; aliased as At[6][100] later
#define L_PB   1600      // Pb[3][16][8] = 384
#define L_WH   1984      // [16][8]
#define L_LW   2112      // [16][8]
#define L_POS  2240      // [16][4]
#define L_MSK  2304      // 16
#define L_SW   2320      // 8
#define L_K1S  2328      // [16][8]
#define L_IDX  2456      // 2 parities x 16 ints
#define LZ     2496
#define B_FLOATS (SH_LANE + 4 * LZ)

__global__ __launch_bounds__(384, 2) void attn_kernel(
    const int* __restrict__ refidx,
    const float* __restrict__ Wp1, const float* __restrict__ bp1,
    const float* __restrict__ gp,  const float* __restrict__ betap,
    const float* __restrict__ Wp2, const float* __restrict__ bp2,
    const float* __restrict__ Ww1, const float* __restrict__ bw1,
    const float* __restrict__ gw,  const float* __restrict__ betaw,
    const float* __restrict__ Ww2, const float* __restrict__ bw2,
    float* __restrict__ out, int n)
{
    extern __shared__ float sm[];
    float* Wp2T  = sm + SH_WP2T;
    float* Fts   = sm + SH_FT;
    float* Wp1f  = sm + SH_WP1F;
    float* bp2s  = sm + SH_BP2;
    float* Ww2s  = sm + SH_WW2;
    float* bw2s  = sm + SH_BW2;
    float* CBs   = sm + SH_CB;
    float* Ww1fs = sm + SH_W1F;
    float* part  = sm + SH_PART;

    const int tid  = threadIdx.x;
    const int pp   = tid / 96;      // point slot 0..3
    const int jr   = tid % 96;      // j / c role
    const int wl   = jr / 32;       // warp within point-lane (0..2)
    const int lane = tid & 31;
    const int sL   = jr & 15, gL = jr >> 4;   // (s,g) role

    float* lzone = sm + SH_LANE + pp * LZ;
    float* hT    = lzone + L_HT;
    float* At    = lzone + L_HT;    // alias
    float* Pb    = lzone + L_PB;
    float* whes  = lzone + L_WH;
    float* l2w   = lzone + L_LW;
    float* poss  = lzone + L_POS;
    float* masks = lzone + L_MSK;
    float* swv   = lzone + L_SW;
    float* K1s   = lzone + L_K1S;
    int*   idxp  = (int*)(lzone + L_IDX);

    const unsigned sb     = smaddr(sm);
    const unsigned ht_b   = sb + 4 * (SH_LANE + pp * LZ + L_HT);
    const unsigned lw_b   = sb + 4 * (SH_LANE + pp * LZ + L_LW);
    const unsigned ft_b   = sb + 4 * SH_FT;
    const unsigned wp2_b  = sb + 4 * SH_WP2T;

    // ---- one-time staging ----
    for (int i = tid; i < 9216; i += 384)
        Wp2T[(i % 96) * 100 + i / 96] = Wp2[i];
    if (tid < 96) {
        float ap = gp[tid] * rsqrtf(1.00001f);
        Wp1f[tid * 4 + 0] = Wp1[tid]       * ap;
        Wp1f[tid * 4 + 1] = Wp1[96 + tid]  * ap;
        Wp1f[tid * 4 + 2] = Wp1[192 + tid] * ap;
        Wp1f[tid * 4 + 3] = bp1[tid] * ap + betap[tid];
        bp2s[tid] = bp2[tid];
    }
    if (tid < 36) Ww2s[tid] = Ww2[tid];
    if (tid < 6)  bw2s[tid] = bw2[tid];
    for (int i = tid; i < 576; i += 384) {
        int g = i % 6;
        Ww1fs[i] = Ww1[i] * (gw[g] * rsqrtf(1.00001f));
    }
    __syncthreads();
    for (int i = tid; i < 576; i += 384) {
        int j = i / 6, g = i % 6;
        float f = 0.f;
        #pragma unroll 8
        for (int c = 0; c < 96; c++) f += Wp2T[c * 100 + j] * Ww1fs[c * 6 + g];
        Fts[g * 100 + j] = f;
    }
    if (tid < 6) {
        float aw = gw[tid] * rsqrtf(1.00001f);
        float cb = bw1[tid] * aw + betaw[tid];
        for (int c = 0; c < 96; c++) cb += bp2s[c] * Ww1fs[c * 6 + tid];
        CBs[tid] = cb;
    }
    __syncthreads();

    int par = 0;
    for (int it = blockIdx.x; it * 4 < n; it += gridDim.x) {
        int nn = it * 4 + pp;
        bool act = (nn < n);

        // ---- ph1: idx / mask / relative positions (coord4) / K1 prefetch ----
        if (act && jr < 16) {
            int raw = refidx[nn * 16 + jr];
            int vv = raw + 1;
            masks[jr] = (vv > 0) ? 1.f : ((vv < 0) ? -1.f : 0.f);
            int idx = (raw < 0) ? raw + n : raw;
            idxp[par * 16 + jr] = idx;
            float4 c0 = g_c4[nn];
            float4 cn = g_c4[idx];
            poss[jr * 4 + 0] = cn.x - c0.x;
            poss[jr * 4 + 1] = cn.y - c0.y;
            poss[jr * 4 + 2] = cn.z - c0.z;
            float4 ka = *(const float4*)&g_K1[idx * 8];
            float4 kb = *(const float4*)&g_K1[idx * 8 + 4];
            *(float4*)&K1s[jr * 8] = ka;
            *(float4*)&K1s[jr * 8 + 4] = kb;
        }
        __syncthreads();

        // ---- ph2: h[s] per thread-j ----
        float h[16];
        if (act) {
            float4 wp = *(const float4*)&Wp1f[jr * 4];
            #pragma unroll
            for (int s = 0; s < 16; s++) {
                float4 p = *(const float4*)&poss[s * 4];
                float hv = fmaxf(wp.w + p.x * wp.x + p.y * wp.y + p.z * wp.z, 0.f);
                h[s] = hv;
                hT[s * 100 + jr] = hv;
            }
        }
        __syncthreads();

        // ---- ph3: l1 partials, j-split across warps. lane = (s, g-triple) ----
        if (act) {
            int s = lane & 15, gt = lane >> 4;
            int j0 = 32 * wl;
            ull ag0 = 0ULL, ag1 = 0ULL, ag2 = 0ULL;
            unsigned hb  = ht_b + (s * 100 + j0) * 4;
            unsigned f0b = ft_b + ((gt * 3 + 0) * 100 + j0) * 4;
            unsigned f1b = f0b + 400;
            unsigned f2b = f1b + 400;
            #pragma unroll
            for (int t = 0; t < 8; t++) {
                ull h01, h23, f01, f23;
                LDS2X64(h01, h23, hb); hb += 16;
                LDS2X64(f01, f23, f0b); f0b += 16;
                FFMA2(ag0, h01, f01, ag0);
                FFMA2(ag0, h23, f23, ag0);
                LDS2X64(f01, f23, f1b); f1b += 16;
                FFMA2(ag1, h01, f01, ag1);
                FFMA2(ag1, h23, f23, ag1);
                LDS2X64(f01, f23, f2b); f2b += 16;
                FFMA2(ag2, h01, f01, ag2);
                FFMA2(ag2, h23, f23, ag2);
            }
            float x0, x1;
            float* pb = Pb + wl * 128 + s * 8 + gt * 4;
            UNPK(x0, x1, ag0); pb[0] = x0 + x1;
            UNPK(x0, x1, ag1); pb[1] = x0 + x1;
            UNPK(x0, x1, ag2); pb[2] = x0 + x1;
        }
        __syncthreads();

        // ---- ph3b: combine partials + K1/Q1, wh = relu(l1) ----
        if (act) {
            int slot = gL + (gL >= 3 ? 1 : 0);
            float l1 = CBs[gL] + K1s[sL * 8 + gL] - g_Q1[nn * 8 + gL]
                     + Pb[0 * 128 + sL * 8 + slot]
                     + Pb[1 * 128 + sL * 8 + slot]
                     + Pb[2 * 128 + sL * 8 + slot];
            whes[sL * 8 + gL] = fmaxf(l1, 0.f);
        }
        __syncthreads();

        // ---- ph456: l2, 16-lane softmax, masked weights ----
        if (act) {
            float l2 = bw2s[gL];
            #pragma unroll
            for (int gg = 0; gg < 6; gg++)
                l2 += whes[sL * 8 + gg] * Ww2s[gg * 6 + gL];
            float mx = l2;
            #pragma unroll
            for (int off = 8; off >= 1; off >>= 1)
                mx = fmaxf(mx, __shfl_xor_sync(0xffffffffu, mx, off, 16));
            float e  = __expf(l2 - mx);
            float em = e * masks[sL];
            float ss = e, ms = em;
            #pragma unroll
            for (int off = 8; off >= 1; off >>= 1) {
                ss += __shfl_xor_sync(0xffffffffu, ss, off, 16);
                ms += __shfl_xor_sync(0xffffffffu, ms, off, 16);
            }
            l2w[sL * 8 + gL] = em / ss;
            if (sL == 0) swv[gL] = ms / ss;
        }
        __syncthreads();

        // ---- ph7: A[j,g] = sum_s h[s,j] w[s,g]  (f32x2) ----
        if (act) {
            ull A01 = 0ULL, A23 = 0ULL, A45 = 0ULL;
            unsigned lb = lw_b;
            #pragma unroll
            for (int s = 0; s < 16; s++) {
                ull w01, w23, w45, w67;
                LDS2X64(w01, w23, lb);
                LDS2X64(w45, w67, lb + 16);
                lb += 32;
                ull hd; DUP2(hd, h[s]);
                FFMA2(A01, hd, w01, A01);
                FFMA2(A23, hd, w23, A23);
                FFMA2(A45, hd, w45, A45);
            }
            float A0, A1, A2, A3, A4, A5;
            UNPK(A0, A1, A01);
            UNPK(A2, A3, A23);
            UNPK(A4, A5, A45);
            At[0 * 100 + jr] = A0; At[1 * 100 + jr] = A1; At[2 * 100 + jr] = A2;
            At[3 * 100 + jr] = A3; At[4 * 100 + jr] = A4; At[5 * 100 + jr] = A5;
        }
        __syncthreads();

        // ---- ph8a: quartered Wp2^T @ A across 4 points (f32x2) ----
        {
            int c = jr, g = jr >> 4, j0 = pp * 24;
            ull pt2[4] = {0ULL, 0ULL, 0ULL, 0ULL};
            unsigned wb = wp2_b + (c * 100 + j0) * 4;
            unsigned ab0 = sb + 4 * (SH_LANE + 0 * LZ + L_HT) + (g * 100 + j0) * 4;
            unsigned ab1 = sb + 4 * (SH_LANE + 1 * LZ + L_HT) + (g * 100 + j0) * 4;
            unsigned ab2 = sb + 4 * (SH_LANE + 2 * LZ + L_HT) + (g * 100 + j0) * 4;
            unsigned ab3 = sb + 4 * (SH_LANE + 3 * LZ + L_HT) + (g * 100 + j0) * 4;
            #pragma unroll
            for (int t = 0; t < 6; t++) {
                ull w01, w23, a01, a23;
                LDS2X64(w01, w23, wb); wb += 16;
                LDS2X64(a01, a23, ab0); ab0 += 16;
                FFMA2(pt2[0], w01, a01, pt2[0]);
                FFMA2(pt2[0], w23, a23, pt2[0]);
                LDS2X64(a01, a23, ab1); ab1 += 16;
                FFMA2(pt2[1], w01, a01, pt2[1]);
                FFMA2(pt2[1], w23, a23, pt2[1]);
                LDS2X64(a01, a23, ab2); ab2 += 16;
                FFMA2(pt2[2], w01, a01, pt2[2]);
                FFMA2(pt2[2], w23, a23, pt2[2]);
                LDS2X64(a01, a23, ab3); ab3 += 16;
                FFMA2(pt2[3], w01, a01, pt2[3]);
                FFMA2(pt2[3], w23, a23, pt2[3]);
            }
            #pragma unroll
            for (int p = 0; p < 4; p++) {
                float lo, hi;
                UNPK(lo, hi, pt2[p]);
                part[(pp * 4 + p) * 96 + c] = lo + hi;
            }
        }
        __syncthreads();

        // ---- ph8b: combine quarters + v-gather term, store out ----
        if (act) {
            int c = jr, g = jr >> 4;
            const int* idq = (const int*)(lzone + L_IDX) + par * 16;
            float o = bp2s[c] * swv[g];
            o += part[(0 * 4 + pp) * 96 + c] + part[(1 * 4 + pp) * 96 + c]
               + part[(2 * 4 + pp) * 96 + c] + part[(3 * 4 + pp) * 96 + c];
            float vv[16];
            #pragma unroll
            for (int s = 0; s < 16; s++)
                vv[s] = g_v[idq[s] * 96 + c];
            #pragma unroll
            for (int s = 0; s < 16; s++)
                o += vv[s] * l2w[s * 8 + g];
            out[nn * 96 + c] = o;
        }
        par ^= 1;
    }
}

extern "C" void kernel_launch(void* const* d_in, const int* in_sizes, int n_in,
                              void* d_out, int out_size) {
    const float* feat  = (const float*)d_in[0];
    const float* coord = (const float*)d_in[1];
    const int*   ref   = (const int*)d_in[2];
    const float* Wq    = (const float*)d_in[3];
    const float* bq    = (const float*)d_in[4];
    const float* gq    = (const float*)d_in[5];
    const float* betaq = (const float*)d_in[6];
    const float* Wk    = (const float*)d_in[7];
    const float* bk    = (const float*)d_in[8];
    const float* gk    = (const float*)d_in[9];
    const float* betak = (const float*)d_in[10];
    const float* Wv    = (const float*)d_in[11];
    const float* bv    = (const float*)d_in[12];
    const float* Wp1   = (const float*)d_in[13];
    const float* bp1   = (const float*)d_in[14];
    const float* gp    = (const float*)d_in[15];
    const float* betap = (const float*)d_in[16];
    const float* Wp2   = (const float*)d_in[17];
    const float* bp2   = (const float*)d_in[18];
    const float* Ww1   = (const float*)d_in[19];
    const float* bw1   = (const float*)d_in[20];
    const float* gw    = (const float*)d_in[21];
    const float* betaw = (const float*)d_in[22];
    const float* Ww2   = (const float*)d_in[23];
    const float* bw2   = (const float*)d_in[24];

    int n = in_sizes[1] / 3;

    int smA = A_FLOATS * (int)sizeof(float);
    int smB = B_FLOATS * (int)sizeof(float);
    cudaFuncSetAttribute(qkv_kernel,  cudaFuncAttributeMaxDynamicSharedMemorySize, smA);
    cudaFuncSetAttribute(attn_kernel, cudaFuncAttributeMaxDynamicSharedMemorySize, smB);

    int blocksA = (n + 63) / 64;
    qkv_kernel<<<blocksA, 192, smA>>>(feat, coord, Wq, bq, gq, betaq,
                                      Wk, bk, gk, betak, Wv, bv, Ww1, gw, n);

    int occ = 0;
    cudaOccupancyMaxActiveBlocksPerMultiprocessor(&occ, attn_kernel, 384, smB);
    if (occ < 1) occ = 1;
    int nsm = 0;
    cudaDeviceGetAttribute(&nsm, cudaDevAttrMultiProcessorCount, 0);
    if (nsm <= 0) nsm = 148;
    int blocksB = occ * nsm;
    int quads = (n + 3) / 4;
    if (blocksB > quads) blocksB = quads;

    attn_kernel<<<blocksB, 384, smB>>>(ref,
                                       Wp1, bp1, gp, betap, Wp2, bp2,
                                       Ww1, bw1, gw, betaw, Ww2, bw2,
                                       (float*)d_out, n);
}

// round 9
// speedup vs baseline: 1.1743x; 1.1743x over previous
#include <cuda_runtime.h>

#define NMAX 50000
#define C 96

__device__ float g_v[NMAX * C];
__device__ float g_Q1[NMAX * 8];
__device__ float g_K1[NMAX * 8];
__device__ float4 g_c4[NMAX];

// ---- f32x2 packed-math helpers (sm_103a) ----
typedef unsigned long long ull;
#define FFMA2(d, a, b, c) \
    asm("fma.rn.f32x2 %0, %1, %2, %3;" : "=l"(d) : "l"(a), "l"(b), "l"(c))
#define LDS2X64(a, b, addr) \
    asm volatile("ld.shared.v2.u64 {%0, %1}, [%2];" : "=l"(a), "=l"(b) : "r"(addr))
#define DUP2(d, f) \
    asm("mov.b64 %0, {%1, %1};" : "=l"(d) : "r"(__float_as_uint(f)))
#define UNPK(lo, hi, p) do { unsigned _ul, _uh; \
    asm("mov.b64 {%0, %1}, %2;" : "=r"(_ul), "=r"(_uh) : "l"(p)); \
    lo = __uint_as_float(_ul); hi = __uint_as_float(_uh); } while (0)

__device__ __forceinline__ unsigned smaddr(const void* p) {
    unsigned r;
    asm("{.reg .u64 t; cvta.to.shared.u64 t, %1; cvt.u32.u64 %0, t;}"
        : "=r"(r) : "l"(p));
    return r;
}

// ---------------------------------------------------------------------------
// Kernel A: v = feat@Wv+bv, Q1 = relu(bn(feat@Wq+bq))@Ww1f, K1 likewise.
// 64 rows/block, 192 threads, 8x4 register tile, f32x2, R7 lane map.
// rows[] aliased onto Ws[] -> smem 65KB -> 2 blocks/SM.
// ---------------------------------------------------------------------------
#define A_FEATT 0            // 96*68 = 6528
#define A_WS    6528         // 96*96 = 9216  (rows[64][100]=6400 aliases here)
#define A_W1T   15744        // Ww1fT[6][100] = 600
#define A_FLOATS 16344

__global__ __launch_bounds__(192) void qkv_kernel(
    const float* __restrict__ feat, const float* __restrict__ coord,
    const float* __restrict__ Wq, const float* __restrict__ bq,
    const float* __restrict__ gq, const float* __restrict__ betaq,
    const float* __restrict__ Wk, const float* __restrict__ bk,
    const float* __restrict__ gk, const float* __restrict__ betak,
    const float* __restrict__ Wv, const float* __restrict__ bv,
    const float* __restrict__ Ww1, const float* __restrict__ gw,
    int n)
{
    extern __shared__ float sm[];
    float* featT = sm + A_FEATT;
    float* Ws    = sm + A_WS;
    float* rows  = sm + A_WS;    // ALIAS: live only after mainloop ends
    float* Ww1fT = sm + A_W1T;   // [6][100]
    const int tid = threadIdx.x;
    const int tx = tid % 24, ty = tid / 24;   // R7 proven map
    const int base = blockIdx.x * 64;

    // pack coord4 for this block's rows
    if (tid < 64) {
        int row = base + tid;
        if (row < n) {
            float4 c;
            c.x = coord[row * 3 + 0];
            c.y = coord[row * 3 + 1];
            c.z = coord[row * 3 + 2];
            c.w = 0.f;
            g_c4[row] = c;
        }
    }

    for (int i = tid; i < 64 * 96; i += 192) {
        int r = i / 96, j = i % 96;
        featT[j * 68 + r] = (base + r < n) ? feat[(base + r) * 96 + j] : 0.f;
    }
    for (int i = tid; i < 600; i += 192) {
        int g = i / 100, c = i % 100;
        Ww1fT[i] = (c < 96) ? Ww1[c * 6 + g] * (gw[g] * rsqrtf(1.00001f)) : 0.f;
    }

    const unsigned fbase  = smaddr(featT) + 8 * ty * 4;
    const unsigned rows_b = smaddr(rows);
    const unsigned w1t_b  = smaddr(Ww1fT);

    for (int m = 0; m < 3; m++) {
        const float* W = (m == 0) ? Wq : ((m == 1) ? Wk : Wv);
        __syncthreads();     // prior epilogue done before Ws overwrite
        for (int i = tid; i < 96 * 96; i += 192) Ws[i] = W[i];
        __syncthreads();

        ull acc2[4][4];
        #pragma unroll
        for (int p = 0; p < 4; p++)
            #pragma unroll
            for (int b = 0; b < 4; b++) acc2[p][b] = 0ULL;

        unsigned fa = fbase;
        #pragma unroll 4
        for (int j = 0; j < 96; j++) {
            ull f01, f23, f45, f67;
            LDS2X64(f01, f23, fa);
            LDS2X64(f45, f67, fa + 16);
            fa += 272;
            float4 w4 = *(const float4*)&Ws[j * 96 + 4 * tx];
            ull wd0, wd1, wd2, wd3;
            DUP2(wd0, w4.x); DUP2(wd1, w4.y); DUP2(wd2, w4.z); DUP2(wd3, w4.w);
            FFMA2(acc2[0][0], f01, wd0, acc2[0][0]);
            FFMA2(acc2[0][1], f01, wd1, acc2[0][1]);
            FFMA2(acc2[0][2], f01, wd2, acc2[0][2]);
            FFMA2(acc2[0][3], f01, wd3, acc2[0][3]);
            FFMA2(acc2[1][0], f23, wd0, acc2[1][0]);
            FFMA2(acc2[1][1], f23, wd1, acc2[1][1]);
            FFMA2(acc2[1][2], f23, wd2, acc2[1][2]);
            FFMA2(acc2[1][3], f23, wd3, acc2[1][3]);
            FFMA2(acc2[2][0], f45, wd0, acc2[2][0]);
            FFMA2(acc2[2][1], f45, wd1, acc2[2][1]);
            FFMA2(acc2[2][2], f45, wd2, acc2[2][2]);
            FFMA2(acc2[2][3], f45, wd3, acc2[2][3]);
            FFMA2(acc2[3][0], f67, wd0, acc2[3][0]);
            FFMA2(acc2[3][1], f67, wd1, acc2[3][1]);
            FFMA2(acc2[3][2], f67, wd2, acc2[3][2]);
            FFMA2(acc2[3][3], f67, wd3, acc2[3][3]);
        }

        float acc[8][4];
        #pragma unroll
        for (int p = 0; p < 4; p++)
            #pragma unroll
            for (int b = 0; b < 4; b++)
                UNPK(acc[2 * p][b], acc[2 * p + 1][b], acc2[p][b]);

        if (m == 2) {
            int c = 4 * tx;
            float4 bb = *(const float4*)&bv[c];
            #pragma unroll
            for (int a = 0; a < 8; a++) {
                int row = base + 8 * ty + a;
                if (row < n) {
                    float4 o = {acc[a][0] + bb.x, acc[a][1] + bb.y,
                                acc[a][2] + bb.z, acc[a][3] + bb.w};
                    *(float4*)&g_v[row * 96 + c] = o;
                }
            }
        } else {
            int c = 4 * tx;
            const float* bsrc = (m == 0) ? bq : bk;
            const float* gsrc = (m == 0) ? gq : gk;
            const float* besrc = (m == 0) ? betaq : betak;
            float4 bb = *(const float4*)&bsrc[c];
            float4 gg = *(const float4*)&gsrc[c];
            float4 be = *(const float4*)&besrc[c];
            float rs = rsqrtf(1.00001f);
            float aa[4] = {gg.x * rs, gg.y * rs, gg.z * rs, gg.w * rs};
            float bba[4] = {bb.x, bb.y, bb.z, bb.w};
            float bea[4] = {be.x, be.y, be.z, be.w};
            __syncthreads();     // all warps done reading Ws before rows alias write
            #pragma unroll
            for (int a = 0; a < 8; a++) {
                float4 o;
                o.x = fmaxf((acc[a][0] + bba[0]) * aa[0] + bea[0], 0.f);
                o.y = fmaxf((acc[a][1] + bba[1]) * aa[1] + bea[1], 0.f);
                o.z = fmaxf((acc[a][2] + bba[2]) * aa[2] + bea[2], 0.f);
                o.w = fmaxf((acc[a][3] + bba[3]) * aa[3] + bea[3], 0.f);
                *(float4*)&rows[(8 * ty + a) * 100 + c] = o;
            }
            __syncthreads();
            float* dst = (m == 0) ? g_Q1 : g_K1;
            #pragma unroll
            for (int rr = 0; rr < 2; rr++) {
                int i = rr * 192 + tid;
                int r = i / 6, g = i % 6;
                ull a01 = 0ULL, a23 = 0ULL;
                unsigned rb = rows_b + r * 400;
                unsigned wb = w1t_b + g * 400;
                #pragma unroll
                for (int t = 0; t < 24; t++) {
                    ull r01, r23, w01, w23;
                    LDS2X64(r01, r23, rb); rb += 16;
                    LDS2X64(w01, w23, wb); wb += 16;
                    FFMA2(a01, r01, w01, a01);
                    FFMA2(a23, r23, w23, a23);
                }
                float l0, l1v, l2v, l3;
                UNPK(l0, l1v, a01); UNPK(l2v, l3, a23);
                if (base + r < n)
                    dst[(base + r) * 8 + g] = (l0 + l2v) + (l1v + l3);
            }
        }
    }
}

// ---------------------------------------------------------------------------
// Kernel B: fused attention. 384 threads = 4 point-lanes x 96. (unchanged R8)
// ---------------------------------------------------------------------------
#define SH_WP2T 0        // [96][100]
#define SH_FT   9600     // [6][100]
#define SH_WP1F 10200    // [96][4]
#define SH_BP2  10584    // 96
#define SH_WW2  10680    // 40
#define SH_BW2  10720    // 8
#define SH_CB   10728    // 8
#define SH_W1F  10736    // 576
#define SH_PART 11312    // [16][96]
#define SH_LANE 12848
// per-lane (floats)
#define L_HT   0         // hT[16][100]; aliased as At[6][100] later
#define L_PB   1600      // Pb[3][16][8] = 384
#define L_WH   1984      // [16][8]
#define L_LW   2112      // [16][8]
#define L_POS  2240      // [16][4]
#define L_MSK  2304      // 16
#define L_SW   2320      // 8
#define L_K1S  2328      // [16][8]
#define L_IDX  2456      // 2 parities x 16 ints
#define LZ     2496
#define B_FLOATS (SH_LANE + 4 * LZ)

__global__ __launch_bounds__(384, 2) void attn_kernel(
    const int* __restrict__ refidx,
    const float* __restrict__ Wp1, const float* __restrict__ bp1,
    const float* __restrict__ gp,  const float* __restrict__ betap,
    const float* __restrict__ Wp2, const float* __restrict__ bp2,
    const float* __restrict__ Ww1, const float* __restrict__ bw1,
    const float* __restrict__ gw,  const float* __restrict__ betaw,
    const float* __restrict__ Ww2, const float* __restrict__ bw2,
    float* __restrict__ out, int n)
{
    extern __shared__ float sm[];
    float* Wp2T  = sm + SH_WP2T;
    float* Fts   = sm + SH_FT;
    float* Wp1f  = sm + SH_WP1F;
    float* bp2s  = sm + SH_BP2;
    float* Ww2s  = sm + SH_WW2;
    float* bw2s  = sm + SH_BW2;
    float* CBs   = sm + SH_CB;
    float* Ww1fs = sm + SH_W1F;
    float* part  = sm + SH_PART;

    const int tid  = threadIdx.x;
    const int pp   = tid / 96;
    const int jr   = tid % 96;
    const int wl   = jr / 32;
    const int lane = tid & 31;
    const int sL   = jr & 15, gL = jr >> 4;

    float* lzone = sm + SH_LANE + pp * LZ;
    float* hT    = lzone + L_HT;
    float* At    = lzone + L_HT;
    float* Pb    = lzone + L_PB;
    float* whes  = lzone + L_WH;
    float* l2w   = lzone + L_LW;
    float* poss  = lzone + L_POS;
    float* masks = lzone + L_MSK;
    float* swv   = lzone + L_SW;
    float* K1s   = lzone + L_K1S;
    int*   idxp  = (int*)(lzone + L_IDX);

    const unsigned sb     = smaddr(sm);
    const unsigned ht_b   = sb + 4 * (SH_LANE + pp * LZ + L_HT);
    const unsigned lw_b   = sb + 4 * (SH_LANE + pp * LZ + L_LW);
    const unsigned ft_b   = sb + 4 * SH_FT;
    const unsigned wp2_b  = sb + 4 * SH_WP2T;

    // ---- one-time staging ----
    for (int i = tid; i < 9216; i += 384)
        Wp2T[(i % 96) * 100 + i / 96] = Wp2[i];
    if (tid < 96) {
        float ap = gp[tid] * rsqrtf(1.00001f);
        Wp1f[tid * 4 + 0] = Wp1[tid]       * ap;
        Wp1f[tid * 4 + 1] = Wp1[96 + tid]  * ap;
        Wp1f[tid * 4 + 2] = Wp1[192 + tid] * ap;
        Wp1f[tid * 4 + 3] = bp1[tid] * ap + betap[tid];
        bp2s[tid] = bp2[tid];
    }
    if (tid < 36) Ww2s[tid] = Ww2[tid];
    if (tid < 6)  bw2s[tid] = bw2[tid];
    for (int i = tid; i < 576; i += 384) {
        int g = i % 6;
        Ww1fs[i] = Ww1[i] * (gw[g] * rsqrtf(1.00001f));
    }
    __syncthreads();
    for (int i = tid; i < 576; i += 384) {
        int j = i / 6, g = i % 6;
        float f = 0.f;
        #pragma unroll 8
        for (int c = 0; c < 96; c++) f += Wp2T[c * 100 + j] * Ww1fs[c * 6 + g];
        Fts[g * 100 + j] = f;
    }
    if (tid < 6) {
        float aw = gw[tid] * rsqrtf(1.00001f);
        float cb = bw1[tid] * aw + betaw[tid];
        for (int c = 0; c < 96; c++) cb += bp2s[c] * Ww1fs[c * 6 + tid];
        CBs[tid] = cb;
    }
    __syncthreads();

    int par = 0;
    for (int it = blockIdx.x; it * 4 < n; it += gridDim.x) {
        int nn = it * 4 + pp;
        bool act = (nn < n);

        // ---- ph1: idx / mask / rel positions (coord4) / K1 prefetch ----
        if (act && jr < 16) {
            int raw = refidx[nn * 16 + jr];
            int vv = raw + 1;
            masks[jr] = (vv > 0) ? 1.f : ((vv < 0) ? -1.f : 0.f);
            int idx = (raw < 0) ? raw + n : raw;
            idxp[par * 16 + jr] = idx;
            float4 c0 = g_c4[nn];
            float4 cn = g_c4[idx];
            poss[jr * 4 + 0] = cn.x - c0.x;
            poss[jr * 4 + 1] = cn.y - c0.y;
            poss[jr * 4 + 2] = cn.z - c0.z;
            float4 ka = *(const float4*)&g_K1[idx * 8];
            float4 kb = *(const float4*)&g_K1[idx * 8 + 4];
            *(float4*)&K1s[jr * 8] = ka;
            *(float4*)&K1s[jr * 8 + 4] = kb;
        }
        __syncthreads();

        // ---- ph2: h[s] per thread-j ----
        float h[16];
        if (act) {
            float4 wp = *(const float4*)&Wp1f[jr * 4];
            #pragma unroll
            for (int s = 0; s < 16; s++) {
                float4 p = *(const float4*)&poss[s * 4];
                float hv = fmaxf(wp.w + p.x * wp.x + p.y * wp.y + p.z * wp.z, 0.f);
                h[s] = hv;
                hT[s * 100 + jr] = hv;
            }
        }
        __syncthreads();

        // ---- ph3: l1 partials, j-split across warps ----
        if (act) {
            int s = lane & 15, gt = lane >> 4;
            int j0 = 32 * wl;
            ull ag0 = 0ULL, ag1 = 0ULL, ag2 = 0ULL;
            unsigned hb  = ht_b + (s * 100 + j0) * 4;
            unsigned f0b = ft_b + ((gt * 3 + 0) * 100 + j0) * 4;
            unsigned f1b = f0b + 400;
            unsigned f2b = f1b + 400;
            #pragma unroll
            for (int t = 0; t < 8; t++) {
                ull h01, h23, f01, f23;
                LDS2X64(h01, h23, hb); hb += 16;
                LDS2X64(f01, f23, f0b); f0b += 16;
                FFMA2(ag0, h01, f01, ag0);
                FFMA2(ag0, h23, f23, ag0);
                LDS2X64(f01, f23, f1b); f1b += 16;
                FFMA2(ag1, h01, f01, ag1);
                FFMA2(ag1, h23, f23, ag1);
                LDS2X64(f01, f23, f2b); f2b += 16;
                FFMA2(ag2, h01, f01, ag2);
                FFMA2(ag2, h23, f23, ag2);
            }
            float x0, x1;
            float* pb = Pb + wl * 128 + s * 8 + gt * 4;
            UNPK(x0, x1, ag0); pb[0] = x0 + x1;
            UNPK(x0, x1, ag1); pb[1] = x0 + x1;
            UNPK(x0, x1, ag2); pb[2] = x0 + x1;
        }
        __syncthreads();

        // ---- ph3b: combine partials + K1/Q1, wh = relu(l1) ----
        if (act) {
            int slot = gL + (gL >= 3 ? 1 : 0);
            float l1 = CBs[gL] + K1s[sL * 8 + gL] - g_Q1[nn * 8 + gL]
                     + Pb[0 * 128 + sL * 8 + slot]
                     + Pb[1 * 128 + sL * 8 + slot]
                     + Pb[2 * 128 + sL * 8 + slot];
            whes[sL * 8 + gL] = fmaxf(l1, 0.f);
        }
        __syncthreads();

        // ---- ph456: l2, 16-lane softmax, masked weights ----
        if (act) {
            float l2 = bw2s[gL];
            #pragma unroll
            for (int gg = 0; gg < 6; gg++)
                l2 += whes[sL * 8 + gg] * Ww2s[gg * 6 + gL];
            float mx = l2;
            #pragma unroll
            for (int off = 8; off >= 1; off >>= 1)
                mx = fmaxf(mx, __shfl_xor_sync(0xffffffffu, mx, off, 16));
            float e  = __expf(l2 - mx);
            float em = e * masks[sL];
            float ss = e, ms = em;
            #pragma unroll
            for (int off = 8; off >= 1; off >>= 1) {
                ss += __shfl_xor_sync(0xffffffffu, ss, off, 16);
                ms += __shfl_xor_sync(0xffffffffu, ms, off, 16);
            }
            l2w[sL * 8 + gL] = em / ss;
            if (sL == 0) swv[gL] = ms / ss;
        }
        __syncthreads();

        // ---- ph7: A[j,g] = sum_s h[s,j] w[s,g]  (f32x2) ----
        if (act) {
            ull A01 = 0ULL, A23 = 0ULL, A45 = 0ULL;
            unsigned lb = lw_b;
            #pragma unroll
            for (int s = 0; s < 16; s++) {
                ull w01, w23, w45, w67;
                LDS2X64(w01, w23, lb);
                LDS2X64(w45, w67, lb + 16);
                lb += 32;
                ull hd; DUP2(hd, h[s]);
                FFMA2(A01, hd, w01, A01);
                FFMA2(A23, hd, w23, A23);
                FFMA2(A45, hd, w45, A45);
            }
            float A0, A1, A2, A3, A4, A5;
            UNPK(A0, A1, A01);
            UNPK(A2, A3, A23);
            UNPK(A4, A5, A45);
            At[0 * 100 + jr] = A0; At[1 * 100 + jr] = A1; At[2 * 100 + jr] = A2;
            At[3 * 100 + jr] = A3; At[4 * 100 + jr] = A4; At[5 * 100 + jr] = A5;
        }
        __syncthreads();

        // ---- ph8a: quartered Wp2^T @ A across 4 points (f32x2) ----
        {
            int c = jr, g = jr >> 4, j0 = pp * 24;
            ull pt2[4] = {0ULL, 0ULL, 0ULL, 0ULL};
            unsigned wb = wp2_b + (c * 100 + j0) * 4;
            unsigned ab0 = sb + 4 * (SH_LANE + 0 * LZ + L_HT) + (g * 100 + j0) * 4;
            unsigned ab1 = sb + 4 * (SH_LANE + 1 * LZ + L_HT) + (g * 100 + j0) * 4;
            unsigned ab2 = sb + 4 * (SH_LANE + 2 * LZ + L_HT) + (g * 100 + j0) * 4;
            unsigned ab3 = sb + 4 * (SH_LANE + 3 * LZ + L_HT) + (g * 100 + j0) * 4;
            #pragma unroll
            for (int t = 0; t < 6; t++) {
                ull w01, w23, a01, a23;
                LDS2X64(w01, w23, wb); wb += 16;
                LDS2X64(a01, a23, ab0); ab0 += 16;
                FFMA2(pt2[0], w01, a01, pt2[0]);
                FFMA2(pt2[0], w23, a23, pt2[0]);
                LDS2X64(a01, a23, ab1); ab1 += 16;
                FFMA2(pt2[1], w01, a01, pt2[1]);
                FFMA2(pt2[1], w23, a23, pt2[1]);
                LDS2X64(a01, a23, ab2); ab2 += 16;
                FFMA2(pt2[2], w01, a01, pt2[2]);
                FFMA2(pt2[2], w23, a23, pt2[2]);
                LDS2X64(a01, a23, ab3); ab3 += 16;
                FFMA2(pt2[3], w01, a01, pt2[3]);
                FFMA2(pt2[3], w23, a23, pt2[3]);
            }
            #pragma unroll
            for (int p = 0; p < 4; p++) {
                float lo, hi;
                UNPK(lo, hi, pt2[p]);
                part[(pp * 4 + p) * 96 + c] = lo + hi;
            }
        }
        __syncthreads();

        // ---- ph8b: combine quarters + v-gather term, store out ----
        if (act) {
            int c = jr, g = jr >> 4;
            const int* idq = (const int*)(lzone + L_IDX) + par * 16;
            float o = bp2s[c] * swv[g];
            o += part[(0 * 4 + pp) * 96 + c] + part[(1 * 4 + pp) * 96 + c]
               + part[(2 * 4 + pp) * 96 + c] + part[(3 * 4 + pp) * 96 + c];
            float vv[16];
            #pragma unroll
            for (int s = 0; s < 16; s++)
                vv[s] = g_v[idq[s] * 96 + c];
            #pragma unroll
            for (int s = 0; s < 16; s++)
                o += vv[s] * l2w[s * 8 + g];
            out[nn * 96 + c] = o;
        }
        par ^= 1;
    }
}

extern "C" void kernel_launch(void* const* d_in, const int* in_sizes, int n_in,
                              void* d_out, int out_size) {
    const float* feat  = (const float*)d_in[0];
    const float* coord = (const float*)d_in[1];
    const int*   ref   = (const int*)d_in[2];
    const float* Wq    = (const float*)d_in[3];
    const float* bq    = (const float*)d_in[4];
    const float* gq    = (const float*)d_in[5];
    const float* betaq = (const float*)d_in[6];
    const float* Wk    = (const float*)d_in[7];
    const float* bk    = (const float*)d_in[8];
    const float* gk    = (const float*)d_in[9];
    const float* betak = (const float*)d_in[10];
    const float* Wv    = (const float*)d_in[11];
    const float* bv    = (const float*)d_in[12];
    const float* Wp1   = (const float*)d_in[13];
    const float* bp1   = (const float*)d_in[14];
    const float* gp    = (const float*)d_in[15];
    const float* betap = (const float*)d_in[16];
    const float* Wp2   = (const float*)d_in[17];
    const float* bp2   = (const float*)d_in[18];
    const float* Ww1   = (const float*)d_in[19];
    const float* bw1   = (const float*)d_in[20];
    const float* gw    = (const float*)d_in[21];
    const float* betaw = (const float*)d_in[22];
    const float* Ww2   = (const float*)d_in[23];
    const float* bw2   = (const float*)d_in[24];

    int n = in_sizes[1] / 3;

    int smA = A_FLOATS * (int)sizeof(float);
    int smB = B_FLOATS * (int)sizeof(float);
    cudaFuncSetAttribute(qkv_kernel,  cudaFuncAttributeMaxDynamicSharedMemorySize, smA);
    cudaFuncSetAttribute(attn_kernel, cudaFuncAttributeMaxDynamicSharedMemorySize, smB);

    int blocksA = (n + 63) / 64;
    qkv_kernel<<<blocksA, 192, smA>>>(feat, coord, Wq, bq, gq, betaq,
                                      Wk, bk, gk, betak, Wv, bv, Ww1, gw, n);

    int occ = 0;
    cudaOccupancyMaxActiveBlocksPerMultiprocessor(&occ, attn_kernel, 384, smB);
    if (occ < 1) occ = 1;
    int nsm = 0;
    cudaDeviceGetAttribute(&nsm, cudaDevAttrMultiProcessorCount, 0);
    if (nsm <= 0) nsm = 148;
    int blocksB = occ * nsm;
    int quads = (n + 3) / 4;
    if (blocksB > quads) blocksB = quads;

    attn_kernel<<<blocksB, 384, smB>>>(ref,
                                       Wp1, bp1, gp, betap, Wp2, bp2,
                                       Ww1, bw1, gw, betaw, Ww2, bw2,
                                       (float*)d_out, n);
}

// round 10
// speedup vs baseline: 1.2026x; 1.0241x over previous
#include <cuda_runtime.h>

#define NMAX 50000
#define C 96

__device__ float g_v[NMAX * C];
__device__ float g_Q1[NMAX * 8];
__device__ float g_K1[NMAX * 8];
__device__ float4 g_c4[NMAX];

// ---- f32x2 packed-math helpers (sm_103a) ----
typedef unsigned long long ull;
#define FFMA2(d, a, b, c) \
    asm("fma.rn.f32x2 %0, %1, %2, %3;" : "=l"(d) : "l"(a), "l"(b), "l"(c))
#define LDS2X64(a, b, addr) \
    asm volatile("ld.shared.v2.u64 {%0, %1}, [%2];" : "=l"(a), "=l"(b) : "r"(addr))
#define DUP2(d, f) \
    asm("mov.b64 %0, {%1, %1};" : "=l"(d) : "r"(__float_as_uint(f)))
#define UNPK(lo, hi, p) do { unsigned _ul, _uh; \
    asm("mov.b64 {%0, %1}, %2;" : "=r"(_ul), "=r"(_uh) : "l"(p)); \
    lo = __uint_as_float(_ul); hi = __uint_as_float(_uh); } while (0)
#define LANE_BAR(id) \
    asm volatile("bar.sync %0, 96;" :: "r"(id) : "memory")

__device__ __forceinline__ unsigned smaddr(const void* p) {
    unsigned r;
    asm("{.reg .u64 t; cvta.to.shared.u64 t, %1; cvt.u32.u64 %0, t;}"
        : "=r"(r) : "l"(p));
    return r;
}

// ---------------------------------------------------------------------------
// Kernel A: v = feat@Wv+bv, Q1 = relu(bn(feat@Wq+bq))@Ww1f, K1 likewise.
// (unchanged from R9: 64 rows/block, 192 thr, 8x4 f32x2 tile, rows aliases Ws)
// ---------------------------------------------------------------------------
#define A_FEATT 0            // 96*68 = 6528
#define A_WS    6528         // 96*96 = 9216  (rows[64][100]=6400 aliases here)
#define A_W1T   15744        // Ww1fT[6][100] = 600
#define A_FLOATS 16344

__global__ __launch_bounds__(192) void qkv_kernel(
    const float* __restrict__ feat, const float* __restrict__ coord,
    const float* __restrict__ Wq, const float* __restrict__ bq,
    const float* __restrict__ gq, const float* __restrict__ betaq,
    const float* __restrict__ Wk, const float* __restrict__ bk,
    const float* __restrict__ gk, const float* __restrict__ betak,
    const float* __restrict__ Wv, const float* __restrict__ bv,
    const float* __restrict__ Ww1, const float* __restrict__ gw,
    int n)
{
    extern __shared__ float sm[];
    float* featT = sm + A_FEATT;
    float* Ws    = sm + A_WS;
    float* rows  = sm + A_WS;    // ALIAS
    float* Ww1fT = sm + A_W1T;
    const int tid = threadIdx.x;
    const int tx = tid % 24, ty = tid / 24;
    const int base = blockIdx.x * 64;

    if (tid < 64) {
        int row = base + tid;
        if (row < n) {
            float4 c;
            c.x = coord[row * 3 + 0];
            c.y = coord[row * 3 + 1];
            c.z = coord[row * 3 + 2];
            c.w = 0.f;
            g_c4[row] = c;
        }
    }

    for (int i = tid; i < 64 * 96; i += 192) {
        int r = i / 96, j = i % 96;
        featT[j * 68 + r] = (base + r < n) ? feat[(base + r) * 96 + j] : 0.f;
    }
    for (int i = tid; i < 600; i += 192) {
        int g = i / 100, c = i % 100;
        Ww1fT[i] = (c < 96) ? Ww1[c * 6 + g] * (gw[g] * rsqrtf(1.00001f)) : 0.f;
    }

    const unsigned fbase  = smaddr(featT) + 8 * ty * 4;
    const unsigned rows_b = smaddr(rows);
    const unsigned w1t_b  = smaddr(Ww1fT);

    for (int m = 0; m < 3; m++) {
        const float* W = (m == 0) ? Wq : ((m == 1) ? Wk : Wv);
        __syncthreads();
        for (int i = tid; i < 96 * 96; i += 192) Ws[i] = W[i];
        __syncthreads();

        ull acc2[4][4];
        #pragma unroll
        for (int p = 0; p < 4; p++)
            #pragma unroll
            for (int b = 0; b < 4; b++) acc2[p][b] = 0ULL;

        unsigned fa = fbase;
        #pragma unroll 4
        for (int j = 0; j < 96; j++) {
            ull f01, f23, f45, f67;
            LDS2X64(f01, f23, fa);
            LDS2X64(f45, f67, fa + 16);
            fa += 272;
            float4 w4 = *(const float4*)&Ws[j * 96 + 4 * tx];
            ull wd0, wd1, wd2, wd3;
            DUP2(wd0, w4.x); DUP2(wd1, w4.y); DUP2(wd2, w4.z); DUP2(wd3, w4.w);
            FFMA2(acc2[0][0], f01, wd0, acc2[0][0]);
            FFMA2(acc2[0][1], f01, wd1, acc2[0][1]);
            FFMA2(acc2[0][2], f01, wd2, acc2[0][2]);
            FFMA2(acc2[0][3], f01, wd3, acc2[0][3]);
            FFMA2(acc2[1][0], f23, wd0, acc2[1][0]);
            FFMA2(acc2[1][1], f23, wd1, acc2[1][1]);
            FFMA2(acc2[1][2], f23, wd2, acc2[1][2]);
            FFMA2(acc2[1][3], f23, wd3, acc2[1][3]);
            FFMA2(acc2[2][0], f45, wd0, acc2[2][0]);
            FFMA2(acc2[2][1], f45, wd1, acc2[2][1]);
            FFMA2(acc2[2][2], f45, wd2, acc2[2][2]);
            FFMA2(acc2[2][3], f45, wd3, acc2[2][3]);
            FFMA2(acc2[3][0], f67, wd0, acc2[3][0]);
            FFMA2(acc2[3][1], f67, wd1, acc2[3][1]);
            FFMA2(acc2[3][2], f67, wd2, acc2[3][2]);
            FFMA2(acc2[3][3], f67, wd3, acc2[3][3]);
        }

        float acc[8][4];
        #pragma unroll
        for (int p = 0; p < 4; p++)
            #pragma unroll
            for (int b = 0; b < 4; b++)
                UNPK(acc[2 * p][b], acc[2 * p + 1][b], acc2[p][b]);

        if (m == 2) {
            int c = 4 * tx;
            float4 bb = *(const float4*)&bv[c];
            #pragma unroll
            for (int a = 0; a < 8; a++) {
                int row = base + 8 * ty + a;
                if (row < n) {
                    float4 o = {acc[a][0] + bb.x, acc[a][1] + bb.y,
                                acc[a][2] + bb.z, acc[a][3] + bb.w};
                    *(float4*)&g_v[row * 96 + c] = o;
                }
            }
        } else {
            int c = 4 * tx;
            const float* bsrc = (m == 0) ? bq : bk;
            const float* gsrc = (m == 0) ? gq : gk;
            const float* besrc = (m == 0) ? betaq : betak;
            float4 bb = *(const float4*)&bsrc[c];
            float4 gg = *(const float4*)&gsrc[c];
            float4 be = *(const float4*)&besrc[c];
            float rs = rsqrtf(1.00001f);
            float aa[4] = {gg.x * rs, gg.y * rs, gg.z * rs, gg.w * rs};
            float bba[4] = {bb.x, bb.y, bb.z, bb.w};
            float bea[4] = {be.x, be.y, be.z, be.w};
            __syncthreads();
            #pragma unroll
            for (int a = 0; a < 8; a++) {
                float4 o;
                o.x = fmaxf((acc[a][0] + bba[0]) * aa[0] + bea[0], 0.f);
                o.y = fmaxf((acc[a][1] + bba[1]) * aa[1] + bea[1], 0.f);
                o.z = fmaxf((acc[a][2] + bba[2]) * aa[2] + bea[2], 0.f);
                o.w = fmaxf((acc[a][3] + bba[3]) * aa[3] + bea[3], 0.f);
                *(float4*)&rows[(8 * ty + a) * 100 + c] = o;
            }
            __syncthreads();
            float* dst = (m == 0) ? g_Q1 : g_K1;
            #pragma unroll
            for (int rr = 0; rr < 2; rr++) {
                int i = rr * 192 + tid;
                int r = i / 6, g = i % 6;
                ull a01 = 0ULL, a23 = 0ULL;
                unsigned rb = rows_b + r * 400;
                unsigned wb = w1t_b + g * 400;
                #pragma unroll
                for (int t = 0; t < 24; t++) {
                    ull r01, r23, w01, w23;
                    LDS2X64(r01, r23, rb); rb += 16;
                    LDS2X64(w01, w23, wb); wb += 16;
                    FFMA2(a01, r01, w01, a01);
                    FFMA2(a23, r23, w23, a23);
                }
                float l0, l1v, l2v, l3;
                UNPK(l0, l1v, a01); UNPK(l2v, l3, a23);
                if (base + r < n)
                    dst[(base + r) * 8 + g] = (l0 + l2v) + (l1v + l3);
            }
        }
    }
}

// ---------------------------------------------------------------------------
// Kernel B: fused attention. 384 threads = 4 point-lanes x 96.
// R9 + pipelined ph1 (double-buffered) + per-lane named barriers.
// ---------------------------------------------------------------------------
#define SH_WP2T 0        // [96][100]
#define SH_FT   9600     // [6][100]
#define SH_WP1F 10200    // [96][4]
#define SH_BP2  10584    // 96
#define SH_WW2  10680    // 40
#define SH_BW2  10720    // 8
#define SH_CB   10728    // 8
#define SH_W1F  10736    // 576
#define SH_PART 11312    // [16][96]
#define SH_LANE 12848
// per-lane (floats)
#define L_HT   0         // hT[16][100]; aliased as At[6][100] later
#define L_PB   1600      // Pb[3][16][8] = 384
#define L_WH   1984      // [16][8]
#define L_LW   2112      // [16][8]
#define L_POS  2240      // 2 x [16][4] = 128
#define L_MSK  2368      // 2 x 16 = 32
#define L_SW   2400      // 8
#define L_K1S  2408      // 2 x [16][8] = 256
#define L_IDX  2664      // 2 x 16 ints = 32
#define LZ     2720
#define B_FLOATS (SH_LANE + 4 * LZ)   // 23728 floats = 94.9 KB

__global__ __launch_bounds__(384, 2) void attn_kernel(
    const int* __restrict__ refidx,
    const float* __restrict__ Wp1, const float* __restrict__ bp1,
    const float* __restrict__ gp,  const float* __restrict__ betap,
    const float* __restrict__ Wp2, const float* __restrict__ bp2,
    const float* __restrict__ Ww1, const float* __restrict__ bw1,
    const float* __restrict__ gw,  const float* __restrict__ betaw,
    const float* __restrict__ Ww2, const float* __restrict__ bw2,
    float* __restrict__ out, int n)
{
    extern __shared__ float sm[];
    float* Wp2T  = sm + SH_WP2T;
    float* Fts   = sm + SH_FT;
    float* Wp1f  = sm + SH_WP1F;
    float* bp2s  = sm + SH_BP2;
    float* Ww2s  = sm + SH_WW2;
    float* bw2s  = sm + SH_BW2;
    float* CBs   = sm + SH_CB;
    float* Ww1fs = sm + SH_W1F;
    float* part  = sm + SH_PART;

    const int tid  = threadIdx.x;
    const int pp   = tid / 96;
    const int jr   = tid % 96;
    const int wl   = jr / 32;
    const int lane = tid & 31;
    const int sL   = jr & 15, gL = jr >> 4;
    const int barid = 1 + pp;

    float* lzone = sm + SH_LANE + pp * LZ;
    float* hT    = lzone + L_HT;
    float* At    = lzone + L_HT;
    float* Pb    = lzone + L_PB;
    float* whes  = lzone + L_WH;
    float* l2w   = lzone + L_LW;
    float* poss  = lzone + L_POS;
    float* masks = lzone + L_MSK;
    float* swv   = lzone + L_SW;
    float* K1s   = lzone + L_K1S;
    int*   idxp  = (int*)(lzone + L_IDX);

    const unsigned sb     = smaddr(sm);
    const unsigned ht_b   = sb + 4 * (SH_LANE + pp * LZ + L_HT);
    const unsigned lw_b   = sb + 4 * (SH_LANE + pp * LZ + L_LW);
    const unsigned ft_b   = sb + 4 * SH_FT;
    const unsigned wp2_b  = sb + 4 * SH_WP2T;

    // ---- one-time staging ----
    for (int i = tid; i < 9216; i += 384)
        Wp2T[(i % 96) * 100 + i / 96] = Wp2[i];
    if (tid < 96) {
        float ap = gp[tid] * rsqrtf(1.00001f);
        Wp1f[tid * 4 + 0] = Wp1[tid]       * ap;
        Wp1f[tid * 4 + 1] = Wp1[96 + tid]  * ap;
        Wp1f[tid * 4 + 2] = Wp1[192 + tid] * ap;
        Wp1f[tid * 4 + 3] = bp1[tid] * ap + betap[tid];
        bp2s[tid] = bp2[tid];
    }
    if (tid < 36) Ww2s[tid] = Ww2[tid];
    if (tid < 6)  bw2s[tid] = bw2[tid];
    for (int i = tid; i < 576; i += 384) {
        int g = i % 6;
        Ww1fs[i] = Ww1[i] * (gw[g] * rsqrtf(1.00001f));
    }
    __syncthreads();
    for (int i = tid; i < 576; i += 384) {
        int j = i / 6, g = i % 6;
        float f = 0.f;
        #pragma unroll 8
        for (int c = 0; c < 96; c++) f += Wp2T[c * 100 + j] * Ww1fs[c * 6 + g];
        Fts[g * 100 + j] = f;
    }
    if (tid < 6) {
        float aw = gw[tid] * rsqrtf(1.00001f);
        float cb = bw1[tid] * aw + betaw[tid];
        for (int c = 0; c < 96; c++) cb += bp2s[c] * Ww1fs[c * 6 + tid];
        CBs[tid] = cb;
    }
    __syncthreads();

    // ---- ph1 loader (warp0: pos/mask/idx; warp1: K1), buffer b ----
    auto load_ph1 = [&](int nn2, int b) {
        if (nn2 < n && lane < 16) {
            if (wl == 0) {
                int raw = refidx[nn2 * 16 + lane];
                int vv = raw + 1;
                masks[b * 16 + lane] = (vv > 0) ? 1.f : ((vv < 0) ? -1.f : 0.f);
                int idx = (raw < 0) ? raw + n : raw;
                idxp[b * 16 + lane] = idx;
                float4 c0 = g_c4[nn2];
                float4 cn = g_c4[idx];
                poss[b * 64 + lane * 4 + 0] = cn.x - c0.x;
                poss[b * 64 + lane * 4 + 1] = cn.y - c0.y;
                poss[b * 64 + lane * 4 + 2] = cn.z - c0.z;
            } else if (wl == 1) {
                int raw = refidx[nn2 * 16 + lane];
                int idx = (raw < 0) ? raw + n : raw;
                float4 ka = *(const float4*)&g_K1[idx * 8];
                float4 kb = *(const float4*)&g_K1[idx * 8 + 4];
                *(float4*)&K1s[b * 128 + lane * 8] = ka;
                *(float4*)&K1s[b * 128 + lane * 8 + 4] = kb;
            }
        }
    };

    // prologue: first iteration's ph1 into buffer 0
    load_ph1(blockIdx.x * 4 + pp, 0);

    int par = 0;
    for (int it = blockIdx.x; it * 4 < n; it += gridDim.x) {
        int nn = it * 4 + pp;
        bool act = (nn < n);

        LANE_BAR(barid);   // ph1[par] visible to this lane

        // ---- ph2: h[s] per thread-j ----
        float h[16];
        if (act) {
            float4 wp = *(const float4*)&Wp1f[jr * 4];
            #pragma unroll
            for (int s = 0; s < 16; s++) {
                float4 p = *(const float4*)&poss[par * 64 + s * 4];
                float hv = fmaxf(wp.w + p.x * wp.x + p.y * wp.y + p.z * wp.z, 0.f);
                h[s] = hv;
                hT[s * 100 + jr] = hv;
            }
        }
        __syncwarp();   // ph3 reads only this warp's hT columns

        // ---- ph3: l1 partials, j-split across warps ----
        if (act) {
            int s = lane & 15, gt = lane >> 4;
            int j0 = 32 * wl;
            ull ag0 = 0ULL, ag1 = 0ULL, ag2 = 0ULL;
            unsigned hb  = ht_b + (s * 100 + j0) * 4;
            unsigned f0b = ft_b + ((gt * 3 + 0) * 100 + j0) * 4;
            unsigned f1b = f0b + 400;
            unsigned f2b = f1b + 400;
            #pragma unroll
            for (int t = 0; t < 8; t++) {
                ull h01, h23, f01, f23;
                LDS2X64(h01, h23, hb); hb += 16;
                LDS2X64(f01, f23, f0b); f0b += 16;
                FFMA2(ag0, h01, f01, ag0);
                FFMA2(ag0, h23, f23, ag0);
                LDS2X64(f01, f23, f1b); f1b += 16;
                FFMA2(ag1, h01, f01, ag1);
                FFMA2(ag1, h23, f23, ag1);
                LDS2X64(f01, f23, f2b); f2b += 16;
                FFMA2(ag2, h01, f01, ag2);
                FFMA2(ag2, h23, f23, ag2);
            }
            float x0, x1;
            float* pb = Pb + wl * 128 + s * 8 + gt * 4;
            UNPK(x0, x1, ag0); pb[0] = x0 + x1;
            UNPK(x0, x1, ag1); pb[1] = x0 + x1;
            UNPK(x0, x1, ag2); pb[2] = x0 + x1;
        }
        LANE_BAR(barid);

        // ---- ph3b: combine partials + K1/Q1, wh = relu(l1) ----
        if (act) {
            int slot = gL + (gL >= 3 ? 1 : 0);
            float l1 = CBs[gL] + K1s[par * 128 + sL * 8 + gL] - g_Q1[nn * 8 + gL]
                     + Pb[0 * 128 + sL * 8 + slot]
                     + Pb[1 * 128 + sL * 8 + slot]
                     + Pb[2 * 128 + sL * 8 + slot];
            whes[sL * 8 + gL] = fmaxf(l1, 0.f);
        }
        LANE_BAR(barid);

        // ---- ph456: l2, 16-lane softmax, masked weights ----
        if (act) {
            float l2 = bw2s[gL];
            #pragma unroll
            for (int gg = 0; gg < 6; gg++)
                l2 += whes[sL * 8 + gg] * Ww2s[gg * 6 + gL];
            float mx = l2;
            #pragma unroll
            for (int off = 8; off >= 1; off >>= 1)
                mx = fmaxf(mx, __shfl_xor_sync(0xffffffffu, mx, off, 16));
            float e  = __expf(l2 - mx);
            float em = e * masks[par * 16 + sL];
            float ss = e, ms = em;
            #pragma unroll
            for (int off = 8; off >= 1; off >>= 1) {
                ss += __shfl_xor_sync(0xffffffffu, ss, off, 16);
                ms += __shfl_xor_sync(0xffffffffu, ms, off, 16);
            }
            l2w[sL * 8 + gL] = em / ss;
            if (sL == 0) swv[gL] = ms / ss;
        }
        LANE_BAR(barid);

        // ---- prefetch next iteration's ph1 into buffer par^1 (overlaps ph7/8) ----
        load_ph1((it + gridDim.x) * 4 + pp, par ^ 1);

        // ---- ph7: A[j,g] = sum_s h[s,j] w[s,g]  (f32x2) ----
        if (act) {
            ull A01 = 0ULL, A23 = 0ULL, A45 = 0ULL;
            unsigned lb = lw_b;
            #pragma unroll
            for (int s = 0; s < 16; s++) {
                ull w01, w23, w45, w67;
                LDS2X64(w01, w23, lb);
                LDS2X64(w45, w67, lb + 16);
                lb += 32;
                ull hd; DUP2(hd, h[s]);
                FFMA2(A01, hd, w01, A01);
                FFMA2(A23, hd, w23, A23);
                FFMA2(A45, hd, w45, A45);
            }
            float A0, A1, A2, A3, A4, A5;
            UNPK(A0, A1, A01);
            UNPK(A2, A3, A23);
            UNPK(A4, A5, A45);
            At[0 * 100 + jr] = A0; At[1 * 100 + jr] = A1; At[2 * 100 + jr] = A2;
            At[3 * 100 + jr] = A3; At[4 * 100 + jr] = A4; At[5 * 100 + jr] = A5;
        }
        __syncthreads();   // cross-lane: ph8a reads all lanes' At

        // ---- ph8a: quartered Wp2^T @ A across 4 points (f32x2) ----
        {
            int c = jr, g = jr >> 4, j0 = pp * 24;
            ull pt2[4] = {0ULL, 0ULL, 0ULL, 0ULL};
            unsigned wb = wp2_b + (c * 100 + j0) * 4;
            unsigned ab0 = sb + 4 * (SH_LANE + 0 * LZ + L_HT) + (g * 100 + j0) * 4;
            unsigned ab1 = sb + 4 * (SH_LANE + 1 * LZ + L_HT) + (g * 100 + j0) * 4;
            unsigned ab2 = sb + 4 * (SH_LANE + 2 * LZ + L_HT) + (g * 100 + j0) * 4;
            unsigned ab3 = sb + 4 * (SH_LANE + 3 * LZ + L_HT) + (g * 100 + j0) * 4;
            #pragma unroll
            for (int t = 0; t < 6; t++) {
                ull w01, w23, a01, a23;
                LDS2X64(w01, w23, wb); wb += 16;
                LDS2X64(a01, a23, ab0); ab0 += 16;
                FFMA2(pt2[0], w01, a01, pt2[0]);
                FFMA2(pt2[0], w23, a23, pt2[0]);
                LDS2X64(a01, a23, ab1); ab1 += 16;
                FFMA2(pt2[1], w01, a01, pt2[1]);
                FFMA2(pt2[1], w23, a23, pt2[1]);
                LDS2X64(a01, a23, ab2); ab2 += 16;
                FFMA2(pt2[2], w01, a01, pt2[2]);
                FFMA2(pt2[2], w23, a23, pt2[2]);
                LDS2X64(a01, a23, ab3); ab3 += 16;
                FFMA2(pt2[3], w01, a01, pt2[3]);
                FFMA2(pt2[3], w23, a23, pt2[3]);
            }
            #pragma unroll
            for (int p = 0; p < 4; p++) {
                float lo, hi;
                UNPK(lo, hi, pt2[p]);
                part[(pp * 4 + p) * 96 + c] = lo + hi;
            }
        }
        __syncthreads();   // cross-lane: ph8b reads all lanes' part

        // ---- ph8b: combine quarters + v-gather term, store out ----
        if (act) {
            int c = jr, g = jr >> 4;
            const int* idq = (const int*)(lzone + L_IDX) + par * 16;
            float o = bp2s[c] * swv[g];
            o += part[(0 * 4 + pp) * 96 + c] + part[(1 * 4 + pp) * 96 + c]
               + part[(2 * 4 + pp) * 96 + c] + part[(3 * 4 + pp) * 96 + c];
            float vv[16];
            #pragma unroll
            for (int s = 0; s < 16; s++)
                vv[s] = g_v[idq[s] * 96 + c];
            #pragma unroll
            for (int s = 0; s < 16; s++)
                o += vv[s] * l2w[s * 8 + g];
            out[nn * 96 + c] = o;
        }
        par ^= 1;
    }
}

extern "C" void kernel_launch(void* const* d_in, const int* in_sizes, int n_in,
                              void* d_out, int out_size) {
    const float* feat  = (const float*)d_in[0];
    const float* coord = (const float*)d_in[1];
    const int*   ref   = (const int*)d_in[2];
    const float* Wq    = (const float*)d_in[3];
    const float* bq    = (const float*)d_in[4];
    const float* gq    = (const float*)d_in[5];
    const float* betaq = (const float*)d_in[6];
    const float* Wk    = (const float*)d_in[7];
    const float* bk    = (const float*)d_in[8];
    const float* gk    = (const float*)d_in[9];
    const float* betak = (const float*)d_in[10];
    const float* Wv    = (const float*)d_in[11];
    const float* bv    = (const float*)d_in[12];
    const float* Wp1   = (const float*)d_in[13];
    const float* bp1   = (const float*)d_in[14];
    const float* gp    = (const float*)d_in[15];
    const float* betap = (const float*)d_in[16];
    const float* Wp2   = (const float*)d_in[17];
    const float* bp2   = (const float*)d_in[18];
    const float* Ww1   = (const float*)d_in[19];
    const float* bw1   = (const float*)d_in[20];
    const float* gw    = (const float*)d_in[21];
    const float* betaw = (const float*)d_in[22];
    const float* Ww2   = (const float*)d_in[23];
    const float* bw2   = (const float*)d_in[24];

    int n = in_sizes[1] / 3;

    int smA = A_FLOATS * (int)sizeof(float);
    int smB = B_FLOATS * (int)sizeof(float);
    cudaFuncSetAttribute(qkv_kernel,  cudaFuncAttributeMaxDynamicSharedMemorySize, smA);
    cudaFuncSetAttribute(attn_kernel, cudaFuncAttributeMaxDynamicSharedMemorySize, smB);

    int blocksA = (n + 63) / 64;
    qkv_kernel<<<blocksA, 192, smA>>>(feat, coord, Wq, bq, gq, betaq,
                                      Wk, bk, gk, betak, Wv, bv, Ww1, gw, n);

    int occ = 0;
    cudaOccupancyMaxActiveBlocksPerMultiprocessor(&occ, attn_kernel, 384, smB);
    if (occ < 1) occ = 1;
    int nsm = 0;
    cudaDeviceGetAttribute(&nsm, cudaDevAttrMultiProcessorCount, 0);
    if (nsm <= 0) nsm = 148;
    int blocksB = occ * nsm;
    int quads = (n + 3) / 4;
    if (blocksB > quads) blocksB = quads;

    attn_kernel<<<blocksB, 384, smB>>>(ref,
                                       Wp1, bp1, gp, betap, Wp2, bp2,
                                       Ww1, bw1, gw, betaw, Ww2, bw2,
                                       (float*)d_out, n);
}